// round 12
// baseline (speedup 1.0000x reference)
#include <cuda_runtime.h>
#include <cuda_bf16.h>

// 4-qubit circuit, algebraically collapsed, SINGLE fused kernel:
//   phase A (per block, redundant): build the fixed 16x16 complex unitary U
//     of the entangling block in smem via shfl pair-exchange (8 warps x 2
//     basis columns = 256 threads exactly).
//   phase B: R6's packed main loop: v = kron of per-wire (cos,sin);
//     y = U v with fma.rn.f32x2 (re,im packed); z = sign-tree over |y|^2.
//
// R12 = R11 with the spill fixed: input loads moved AFTER phase A (R11
// prefetched x0/x1 across the init phase -> +8 live regs over the 128-reg
// cap -> spills, alu 12%, +3.9us). Phase B register demand is now identical
// to R6's proven spill-free 128.

#define N_QUBITS 4
#define N_LAYERS 6
#define N_AMPS   16
#define THREADS  256
#define NBATCH   512        // samples per block (NB=2 per thread)
#define U_F4     128        // 16x16 complex = 256 float2 = 128 x 16B slots

__device__ __forceinline__ unsigned long long pack2(float lo, float hi) {
    unsigned long long r;
    asm("mov.b64 %0, {%1, %2};" : "=l"(r) : "f"(lo), "f"(hi));
    return r;
}

__device__ __forceinline__ void embed_pq(const float4 x, float* P, float* Q) {
    float c0, s0, c1, s1, c2, s2, c3, s3;
    __sincosf(x.x * 0.5f, &s0, &c0);
    __sincosf(x.y * 0.5f, &s1, &c1);
    __sincosf(x.z * 0.5f, &s2, &c2);
    __sincosf(x.w * 0.5f, &s3, &c3);
    P[0] = c0 * c1; P[1] = c0 * s1; P[2] = s0 * c1; P[3] = s0 * s1;
    Q[0] = c2 * c3; Q[1] = c2 * s3; Q[2] = s2 * c3; Q[3] = s2 * s3;
}

__device__ __forceinline__ float4 readout(const unsigned long long* y) {
    float p[N_AMPS];
    #pragma unroll
    for (int m = 0; m < N_AMPS; m++) {
        float re, im;
        asm("mov.b64 {%0, %1}, %2;" : "=f"(re), "=f"(im) : "l"(y[m]));
        p[m] = re * re + im * im;
    }
    float a0 = p[0]  + p[1],  a1 = p[2]  + p[3],  a2 = p[4]  + p[5],  a3 = p[6]  + p[7];
    float a4 = p[8]  + p[9],  a5 = p[10] + p[11], a6 = p[12] + p[13], a7 = p[14] + p[15];
    float z3 = ((p[0] - p[1]) + (p[2] - p[3])) + ((p[4] - p[5]) + (p[6] - p[7]))
             + ((p[8] - p[9]) + (p[10] - p[11])) + ((p[12] - p[13]) + (p[14] - p[15]));
    float b0 = a0 + a1, b1 = a2 + a3, b2 = a4 + a5, b3 = a6 + a7;
    float z2 = ((a0 - a1) + (a2 - a3)) + ((a4 - a5) + (a6 - a7));
    float z1 = (b0 - b1) + (b2 - b3);
    float z0 = (b0 + b1) - (b2 + b3);
    return make_float4(z0, z1, z2, z3);
}

__global__ void __launch_bounds__(THREADS, 2)
quantum_fused_kernel(const float* __restrict__ inputs,
                     const float* __restrict__ w,
                     float* __restrict__ out) {
    __shared__ float4 sU[U_F4];                    // col i: float2 [i*16, i*16+16)
    __shared__ float4 gm[N_LAYERS * N_QUBITS][2];  // per-gate (u00,u01),(u10,u11)

    const int t    = threadIdx.x;
    const int lane = t & 31;

    // ---- phase A: build U in smem (every block, redundant) ----
    if (t < N_LAYERS * N_QUBITS) {
        float phi   = w[t * 3 + 0];
        float theta = w[t * 3 + 1];
        float omega = w[t * 3 + 2];
        float st, ct, sp, cp, sm, cm;
        __sincosf(theta * 0.5f, &st, &ct);
        __sincosf((phi + omega) * 0.5f, &sp, &cp);
        __sincosf((phi - omega) * 0.5f, &sm, &cm);
        gm[t][0] = make_float4( cp * ct, -sp * ct,   // u00
                               -cm * st, -sm * st);  // u01
        gm[t][1] = make_float4( cm * st, -sm * st,   // u10
                                cp * ct,  sp * ct);  // u11
    }
    __syncthreads();

    {
        // 8 warps x 2 basis columns; 16 lanes per column, one amplitude/lane
        int lane16 = lane & 15;
        int col    = (t >> 5) * 2 + (lane >> 4);
        float re = (lane16 == col) ? 1.0f : 0.0f;
        float im = 0.0f;

        #pragma unroll
        for (int l = 0; l < N_LAYERS; l++) {
            #pragma unroll
            for (int q = 0; q < N_QUBITS; q++) {
                int idx = l * N_QUBITS + q;
                float4 row0 = gm[idx][0];
                float4 row1 = gm[idx][1];
                const int stride = 8 >> q;
                int bit = lane16 & stride;
                float pre = __shfl_xor_sync(0xffffffffu, re, stride);
                float pim = __shfl_xor_sync(0xffffffffu, im, stride);
                float c0r = bit ? row1.x : row0.x,  c0i = bit ? row1.y : row0.y;
                float c1r = bit ? row1.z : row0.z,  c1i = bit ? row1.w : row0.w;
                float a0r = bit ? pre : re,  a0i = bit ? pim : im;
                float a1r = bit ? re : pre,  a1i = bit ? im : pim;
                float nre = c0r * a0r - c0i * a0i + c1r * a1r - c1i * a1i;
                float nim = c0r * a0i + c0i * a0r + c1r * a1i + c1i * a1r;
                re = nre; im = nim;
            }
            const int r = l % (N_QUBITS - 1) + 1;
            #pragma unroll
            for (int q = 0; q < N_QUBITS; q++) {
                const int cbit = 8 >> q, tbit = 8 >> ((q + r) % N_QUBITS);
                float pre = __shfl_xor_sync(0xffffffffu, re, tbit);
                float pim = __shfl_xor_sync(0xffffffffu, im, tbit);
                bool flip = (lane16 & cbit) != 0;
                re = flip ? pre : re;
                im = flip ? pim : im;
            }
        }
        float2* sU2f = reinterpret_cast<float2*>(sU);
        sU2f[col * N_AMPS + lane16] = make_float2(re, im);
    }
    __syncthreads();

    // ---- phase B: per-thread 2 samples, packed matvec (R6 loop) ----
    // inputs loaded only now, so phase A holds no extra live registers
    const int b0 = blockIdx.x * NBATCH + t;
    const int b1 = b0 + THREADS;
    const float4* in4 = reinterpret_cast<const float4*>(inputs);
    float4 x0 = __ldg(in4 + b0);
    float4 x1 = __ldg(in4 + b1);

    const ulonglong2* sU2 = reinterpret_cast<const ulonglong2*>(sU);

    float P0[4], Q0[4], P1[4], Q1[4];
    embed_pq(x0, P0, Q0);
    embed_pq(x1, P1, Q1);

    unsigned long long y0[N_AMPS], y1[N_AMPS];

    // i = 0: initialize accumulators with packed MUL
    {
        float va = P0[0] * Q0[0];
        float vb = P1[0] * Q1[0];
        unsigned long long vp0 = pack2(va, va);
        unsigned long long vp1 = pack2(vb, vb);
        #pragma unroll
        for (int j = 0; j < 8; j++) {
            ulonglong2 uu = sU2[j];
            asm("mul.rn.f32x2 %0, %1, %2;" : "=l"(y0[2*j    ]) : "l"(uu.x), "l"(vp0));
            asm("mul.rn.f32x2 %0, %1, %2;" : "=l"(y0[2*j + 1]) : "l"(uu.y), "l"(vp0));
            asm("mul.rn.f32x2 %0, %1, %2;" : "=l"(y1[2*j    ]) : "l"(uu.x), "l"(vp1));
            asm("mul.rn.f32x2 %0, %1, %2;" : "=l"(y1[2*j + 1]) : "l"(uu.y), "l"(vp1));
        }
    }

    // i = 1..15: packed FFMA accumulate
    #pragma unroll
    for (int i = 1; i < N_AMPS; i++) {
        float va = P0[i >> 2] * Q0[i & 3];
        float vb = P1[i >> 2] * Q1[i & 3];
        unsigned long long vp0 = pack2(va, va);
        unsigned long long vp1 = pack2(vb, vb);
        #pragma unroll
        for (int j = 0; j < 8; j++) {
            ulonglong2 uu = sU2[i * 8 + j];
            asm("fma.rn.f32x2 %0, %1, %2, %0;" : "+l"(y0[2*j    ]) : "l"(uu.x), "l"(vp0));
            asm("fma.rn.f32x2 %0, %1, %2, %0;" : "+l"(y0[2*j + 1]) : "l"(uu.y), "l"(vp0));
            asm("fma.rn.f32x2 %0, %1, %2, %0;" : "+l"(y1[2*j    ]) : "l"(uu.x), "l"(vp1));
            asm("fma.rn.f32x2 %0, %1, %2, %0;" : "+l"(y1[2*j + 1]) : "l"(uu.y), "l"(vp1));
        }
    }

    float4* out4 = reinterpret_cast<float4*>(out);
    out4[b0] = readout(y0);
    out4[b1] = readout(y1);
}

extern "C" void kernel_launch(void* const* d_in, const int* in_sizes, int n_in,
                              void* d_out, int out_size) {
    const float* inputs  = (const float*)d_in[0];   // (B, 4) float32
    const float* weights = (const float*)d_in[1];   // (6, 4, 3) float32
    float* out = (float*)d_out;                     // (B, 4) float32
    int B = in_sizes[0] / N_QUBITS;

    int blocks = B / NBATCH;                        // 262144 / 512 = 512
    quantum_fused_kernel<<<blocks, THREADS>>>(inputs, weights, out);
}

// round 13
// speedup vs baseline: 1.0194x; 1.0194x over previous
#include <cuda_runtime.h>
#include <cuda_bf16.h>

// 4-qubit circuit, algebraically collapsed, SINGLE fused kernel:
//   phase A (per block, redundant): build the fixed 16x16 complex unitary U
//     of the entangling block in smem via shfl pair-exchange.
//   phase B: R6's packed main loop: v = kron of per-wire (cos,sin);
//     y = U v with fma.rn.f32x2 (re,im packed); z = sign-tree over |y|^2.
//
// R13: phase A's layer loop is ROLLED (#pragma unroll 1). R11/R12's spills
// (alu ~12%, +3.7us) came from fully unrolling 6 layers x 4 gates of init:
// ptxas hoisted the whole dataflow into one live window > 128 regs. Rolling
// the l-loop caps phase A's live set at one layer (~20 regs); phase B is
// unchanged from R6's spill-free shape.

#define N_QUBITS 4
#define N_LAYERS 6
#define N_AMPS   16
#define THREADS  256
#define NBATCH   512        // samples per block (NB=2 per thread)
#define U_F4     128        // 16x16 complex = 256 float2 = 128 x 16B slots

__device__ __forceinline__ unsigned long long pack2(float lo, float hi) {
    unsigned long long r;
    asm("mov.b64 %0, {%1, %2};" : "=l"(r) : "f"(lo), "f"(hi));
    return r;
}

__device__ __forceinline__ void embed_pq(const float4 x, float* P, float* Q) {
    float c0, s0, c1, s1, c2, s2, c3, s3;
    __sincosf(x.x * 0.5f, &s0, &c0);
    __sincosf(x.y * 0.5f, &s1, &c1);
    __sincosf(x.z * 0.5f, &s2, &c2);
    __sincosf(x.w * 0.5f, &s3, &c3);
    P[0] = c0 * c1; P[1] = c0 * s1; P[2] = s0 * c1; P[3] = s0 * s1;
    Q[0] = c2 * c3; Q[1] = c2 * s3; Q[2] = s2 * c3; Q[3] = s2 * s3;
}

__device__ __forceinline__ float4 readout(const unsigned long long* y) {
    float p[N_AMPS];
    #pragma unroll
    for (int m = 0; m < N_AMPS; m++) {
        float re, im;
        asm("mov.b64 {%0, %1}, %2;" : "=f"(re), "=f"(im) : "l"(y[m]));
        p[m] = re * re + im * im;
    }
    float a0 = p[0]  + p[1],  a1 = p[2]  + p[3],  a2 = p[4]  + p[5],  a3 = p[6]  + p[7];
    float a4 = p[8]  + p[9],  a5 = p[10] + p[11], a6 = p[12] + p[13], a7 = p[14] + p[15];
    float z3 = ((p[0] - p[1]) + (p[2] - p[3])) + ((p[4] - p[5]) + (p[6] - p[7]))
             + ((p[8] - p[9]) + (p[10] - p[11])) + ((p[12] - p[13]) + (p[14] - p[15]));
    float b0 = a0 + a1, b1 = a2 + a3, b2 = a4 + a5, b3 = a6 + a7;
    float z2 = ((a0 - a1) + (a2 - a3)) + ((a4 - a5) + (a6 - a7));
    float z1 = (b0 - b1) + (b2 - b3);
    float z0 = (b0 + b1) - (b2 + b3);
    return make_float4(z0, z1, z2, z3);
}

__global__ void __launch_bounds__(THREADS, 2)
quantum_fused_kernel(const float* __restrict__ inputs,
                     const float* __restrict__ w,
                     float* __restrict__ out) {
    __shared__ float4 sU[U_F4];                    // col i: float2 [i*16, i*16+16)
    __shared__ float4 gm[N_LAYERS * N_QUBITS][2];  // per-gate (u00,u01),(u10,u11)

    const int t    = threadIdx.x;
    const int lane = t & 31;

    // ---- phase A: build U in smem (every block, redundant) ----
    if (t < N_LAYERS * N_QUBITS) {
        float phi   = w[t * 3 + 0];
        float theta = w[t * 3 + 1];
        float omega = w[t * 3 + 2];
        float st, ct, sp, cp, sm, cm;
        __sincosf(theta * 0.5f, &st, &ct);
        __sincosf((phi + omega) * 0.5f, &sp, &cp);
        __sincosf((phi - omega) * 0.5f, &sm, &cm);
        gm[t][0] = make_float4( cp * ct, -sp * ct,   // u00
                               -cm * st, -sm * st);  // u01
        gm[t][1] = make_float4( cm * st, -sm * st,   // u10
                                cp * ct,  sp * ct);  // u11
    }
    __syncthreads();

    {
        // 8 warps x 2 basis columns; 16 lanes per column, one amplitude/lane
        int lane16 = lane & 15;
        int col    = (t >> 5) * 2 + (lane >> 4);
        float re = (lane16 == col) ? 1.0f : 0.0f;
        float im = 0.0f;

        #pragma unroll 1          // ROLLED: cap phase A's live register window
        for (int l = 0; l < N_LAYERS; l++) {
            #pragma unroll
            for (int q = 0; q < N_QUBITS; q++) {
                float4 row0 = gm[l * N_QUBITS + q][0];
                float4 row1 = gm[l * N_QUBITS + q][1];
                const int stride = 8 >> q;
                int bit = lane16 & stride;
                float pre = __shfl_xor_sync(0xffffffffu, re, stride);
                float pim = __shfl_xor_sync(0xffffffffu, im, stride);
                float c0r = bit ? row1.x : row0.x,  c0i = bit ? row1.y : row0.y;
                float c1r = bit ? row1.z : row0.z,  c1i = bit ? row1.w : row0.w;
                float a0r = bit ? pre : re,  a0i = bit ? pim : im;
                float a1r = bit ? re : pre,  a1i = bit ? im : pim;
                float nre = c0r * a0r - c0i * a0i + c1r * a1r - c1i * a1i;
                float nim = c0r * a0i + c0i * a0r + c1r * a1i + c1i * a1r;
                re = nre; im = nim;
            }
            const int r = l % (N_QUBITS - 1) + 1;   // runtime ring range
            #pragma unroll
            for (int q = 0; q < N_QUBITS; q++) {
                const int cbit = 8 >> q;
                int tbit = 8 >> ((q + r) & 3);      // runtime shfl mask (legal)
                float pre = __shfl_xor_sync(0xffffffffu, re, tbit);
                float pim = __shfl_xor_sync(0xffffffffu, im, tbit);
                bool flip = (lane16 & cbit) != 0;
                re = flip ? pre : re;
                im = flip ? pim : im;
            }
        }
        float2* sU2f = reinterpret_cast<float2*>(sU);
        sU2f[col * N_AMPS + lane16] = make_float2(re, im);
    }
    __syncthreads();

    // ---- phase B: per-thread 2 samples, packed matvec (R6 loop) ----
    const int b0 = blockIdx.x * NBATCH + t;
    const int b1 = b0 + THREADS;
    const float4* in4 = reinterpret_cast<const float4*>(inputs);
    float4 x0 = __ldg(in4 + b0);
    float4 x1 = __ldg(in4 + b1);

    const ulonglong2* sU2 = reinterpret_cast<const ulonglong2*>(sU);

    float P0[4], Q0[4], P1[4], Q1[4];
    embed_pq(x0, P0, Q0);
    embed_pq(x1, P1, Q1);

    unsigned long long y0[N_AMPS], y1[N_AMPS];

    // i = 0: initialize accumulators with packed MUL
    {
        float va = P0[0] * Q0[0];
        float vb = P1[0] * Q1[0];
        unsigned long long vp0 = pack2(va, va);
        unsigned long long vp1 = pack2(vb, vb);
        #pragma unroll
        for (int j = 0; j < 8; j++) {
            ulonglong2 uu = sU2[j];
            asm("mul.rn.f32x2 %0, %1, %2;" : "=l"(y0[2*j    ]) : "l"(uu.x), "l"(vp0));
            asm("mul.rn.f32x2 %0, %1, %2;" : "=l"(y0[2*j + 1]) : "l"(uu.y), "l"(vp0));
            asm("mul.rn.f32x2 %0, %1, %2;" : "=l"(y1[2*j    ]) : "l"(uu.x), "l"(vp1));
            asm("mul.rn.f32x2 %0, %1, %2;" : "=l"(y1[2*j + 1]) : "l"(uu.y), "l"(vp1));
        }
    }

    // i = 1..15: packed FFMA accumulate
    #pragma unroll
    for (int i = 1; i < N_AMPS; i++) {
        float va = P0[i >> 2] * Q0[i & 3];
        float vb = P1[i >> 2] * Q1[i & 3];
        unsigned long long vp0 = pack2(va, va);
        unsigned long long vp1 = pack2(vb, vb);
        #pragma unroll
        for (int j = 0; j < 8; j++) {
            ulonglong2 uu = sU2[i * 8 + j];
            asm("fma.rn.f32x2 %0, %1, %2, %0;" : "+l"(y0[2*j    ]) : "l"(uu.x), "l"(vp0));
            asm("fma.rn.f32x2 %0, %1, %2, %0;" : "+l"(y0[2*j + 1]) : "l"(uu.y), "l"(vp0));
            asm("fma.rn.f32x2 %0, %1, %2, %0;" : "+l"(y1[2*j    ]) : "l"(uu.x), "l"(vp1));
            asm("fma.rn.f32x2 %0, %1, %2, %0;" : "+l"(y1[2*j + 1]) : "l"(uu.y), "l"(vp1));
        }
    }

    float4* out4 = reinterpret_cast<float4*>(out);
    out4[b0] = readout(y0);
    out4[b1] = readout(y1);
}

extern "C" void kernel_launch(void* const* d_in, const int* in_sizes, int n_in,
                              void* d_out, int out_size) {
    const float* inputs  = (const float*)d_in[0];   // (B, 4) float32
    const float* weights = (const float*)d_in[1];   // (6, 4, 3) float32
    float* out = (float*)d_out;                     // (B, 4) float32
    int B = in_sizes[0] / N_QUBITS;

    int blocks = B / NBATCH;                        // 262144 / 512 = 512
    quantum_fused_kernel<<<blocks, THREADS>>>(inputs, weights, out);
}

// round 14
// speedup vs baseline: 1.0396x; 1.0198x over previous
#include <cuda_runtime.h>
#include <cuda_bf16.h>

// 4-qubit circuit, algebraically collapsed (two kernels, R6 structure):
//   init (1 block, 256 thr): build fixed 16x16 complex unitary U via shfl.
//   main: v = kron of per-wire (cos,sin); y = U v with fma.rn.f32x2;
//         z = sign-tree over |y|^2.
//
// R14 = R6 + latency fix: launch_bounds(128,3) raises the reg budget
// ~128->170 so ptxas can hold a 2-deep U-load pipeline (explicit nxt[]
// double-buffer): i+1's 8 LDS.128 issue before i's 32 FFMA2 (64 pipe-cyc
// > 29-cyc LDS latency -> covered in-warp). R6 at the exact 128-reg cap
// had zero prefetch headroom -> 54% full-stall cycles (convoying warps).

#define N_QUBITS 4
#define N_LAYERS 6
#define N_AMPS   16
#define THREADS  128
#define U_F4     128        // 16x16 complex = 256 float2 = 128 x 16B slots

__device__ float4 g_U[U_F4];   // col i: float2 slots [i*16, i*16+16); m-th = U[m][i]

// ---------------- init: evolve 16 basis columns, shfl pair-exchange ----------------
__global__ void init_u_kernel(const float* __restrict__ w) {
    __shared__ float4 gm[N_LAYERS * N_QUBITS][2];
    int t = threadIdx.x;
    if (t < N_LAYERS * N_QUBITS) {
        float phi   = w[t * 3 + 0];
        float theta = w[t * 3 + 1];
        float omega = w[t * 3 + 2];
        float st, ct, sp, cp, sm, cm;
        __sincosf(theta * 0.5f, &st, &ct);
        __sincosf((phi + omega) * 0.5f, &sp, &cp);
        __sincosf((phi - omega) * 0.5f, &sm, &cm);
        gm[t][0] = make_float4( cp * ct, -sp * ct,   // u00
                               -cm * st, -sm * st);  // u01
        gm[t][1] = make_float4( cm * st, -sm * st,   // u10
                                cp * ct,  sp * ct);  // u11
    }
    __syncthreads();

    // 256 threads = 8 warps; each warp evolves 2 columns (16 lanes each).
    int lane   = t & 31;
    int lane16 = lane & 15;
    int col    = (t >> 5) * 2 + (lane >> 4);
    float re = (lane16 == col) ? 1.0f : 0.0f;
    float im = 0.0f;

    #pragma unroll
    for (int l = 0; l < N_LAYERS; l++) {
        #pragma unroll
        for (int q = 0; q < N_QUBITS; q++) {
            int idx = l * N_QUBITS + q;
            float4 row0 = gm[idx][0];
            float4 row1 = gm[idx][1];
            const int stride = 8 >> q;
            int bit = lane16 & stride;
            float pre = __shfl_xor_sync(0xffffffffu, re, stride);
            float pim = __shfl_xor_sync(0xffffffffu, im, stride);
            float c0r = bit ? row1.x : row0.x,  c0i = bit ? row1.y : row0.y;
            float c1r = bit ? row1.z : row0.z,  c1i = bit ? row1.w : row0.w;
            float a0r = bit ? pre : re,  a0i = bit ? pim : im;
            float a1r = bit ? re : pre,  a1i = bit ? im : pim;
            float nre = c0r * a0r - c0i * a0i + c1r * a1r - c1i * a1i;
            float nim = c0r * a0i + c0i * a0r + c1r * a1i + c1i * a1r;
            re = nre; im = nim;
        }
        const int r = l % (N_QUBITS - 1) + 1;
        #pragma unroll
        for (int q = 0; q < N_QUBITS; q++) {
            const int cbit = 8 >> q, tbit = 8 >> ((q + r) % N_QUBITS);
            float pre = __shfl_xor_sync(0xffffffffu, re, tbit);
            float pim = __shfl_xor_sync(0xffffffffu, im, tbit);
            bool flip = (lane16 & cbit) != 0;
            re = flip ? pre : re;
            im = flip ? pim : im;
        }
    }
    float2* U = reinterpret_cast<float2*>(g_U);
    U[col * N_AMPS + lane16] = make_float2(re, im);
}

// ---------------- main ----------------
__device__ __forceinline__ unsigned long long pack2(float lo, float hi) {
    unsigned long long r;
    asm("mov.b64 %0, {%1, %2};" : "=l"(r) : "f"(lo), "f"(hi));
    return r;
}

__device__ __forceinline__ float4 readout(const unsigned long long* y) {
    float p[N_AMPS];
    #pragma unroll
    for (int m = 0; m < N_AMPS; m++) {
        float re, im;
        asm("mov.b64 {%0, %1}, %2;" : "=f"(re), "=f"(im) : "l"(y[m]));
        p[m] = re * re + im * im;
    }
    float a0 = p[0]  + p[1],  a1 = p[2]  + p[3],  a2 = p[4]  + p[5],  a3 = p[6]  + p[7];
    float a4 = p[8]  + p[9],  a5 = p[10] + p[11], a6 = p[12] + p[13], a7 = p[14] + p[15];
    float z3 = ((p[0] - p[1]) + (p[2] - p[3])) + ((p[4] - p[5]) + (p[6] - p[7]))
             + ((p[8] - p[9]) + (p[10] - p[11])) + ((p[12] - p[13]) + (p[14] - p[15]));
    float b0 = a0 + a1, b1 = a2 + a3, b2 = a4 + a5, b3 = a6 + a7;
    float z2 = ((a0 - a1) + (a2 - a3)) + ((a4 - a5) + (a6 - a7));
    float z1 = (b0 - b1) + (b2 - b3);
    float z0 = (b0 + b1) - (b2 + b3);
    return make_float4(z0, z1, z2, z3);
}

__device__ __forceinline__ void embed_pq(const float4 x, float* P, float* Q) {
    float c0, s0, c1, s1, c2, s2, c3, s3;
    __sincosf(x.x * 0.5f, &s0, &c0);
    __sincosf(x.y * 0.5f, &s1, &c1);
    __sincosf(x.z * 0.5f, &s2, &c2);
    __sincosf(x.w * 0.5f, &s3, &c3);
    P[0] = c0 * c1; P[1] = c0 * s1; P[2] = s0 * c1; P[3] = s0 * s1;
    Q[0] = c2 * c3; Q[1] = c2 * s3; Q[2] = s2 * c3; Q[3] = s2 * s3;
}

__global__ void __launch_bounds__(THREADS, 3)
quantum_main_kernel(const float* __restrict__ inputs,
                    float* __restrict__ out) {
    __shared__ float4 sU[U_F4];
    sU[threadIdx.x] = g_U[threadIdx.x];     // THREADS == U_F4
    __syncthreads();
    const ulonglong2* sU2 = reinterpret_cast<const ulonglong2*>(sU);

    const int b0 = blockIdx.x * (THREADS * 2) + threadIdx.x;
    const int b1 = b0 + THREADS;
    const float4* in4 = reinterpret_cast<const float4*>(inputs);

    float P0[4], Q0[4], P1[4], Q1[4];
    embed_pq(__ldg(in4 + b0), P0, Q0);
    embed_pq(__ldg(in4 + b1), P1, Q1);

    unsigned long long y0[N_AMPS], y1[N_AMPS];

    // software-pipelined U loads: buf = column i, nxt = column i+1
    ulonglong2 buf[8];
    #pragma unroll
    for (int j = 0; j < 8; j++) buf[j] = sU2[j];

    // ---- i = 0: init accumulators with packed MUL (prefetch col 1 first) ----
    {
        ulonglong2 nxt[8];
        #pragma unroll
        for (int j = 0; j < 8; j++) nxt[j] = sU2[8 + j];
        float va = P0[0] * Q0[0];
        float vb = P1[0] * Q1[0];
        unsigned long long vp0 = pack2(va, va);
        unsigned long long vp1 = pack2(vb, vb);
        #pragma unroll
        for (int j = 0; j < 8; j++) {
            asm("mul.rn.f32x2 %0, %1, %2;" : "=l"(y0[2*j    ]) : "l"(buf[j].x), "l"(vp0));
            asm("mul.rn.f32x2 %0, %1, %2;" : "=l"(y0[2*j + 1]) : "l"(buf[j].y), "l"(vp0));
            asm("mul.rn.f32x2 %0, %1, %2;" : "=l"(y1[2*j    ]) : "l"(buf[j].x), "l"(vp1));
            asm("mul.rn.f32x2 %0, %1, %2;" : "=l"(y1[2*j + 1]) : "l"(buf[j].y), "l"(vp1));
        }
        #pragma unroll
        for (int j = 0; j < 8; j++) buf[j] = nxt[j];
    }

    // ---- i = 1..15: packed FFMA, prefetch column i+1 before using column i ----
    #pragma unroll
    for (int i = 1; i < N_AMPS; i++) {
        ulonglong2 nxt[8];
        if (i < N_AMPS - 1) {
            #pragma unroll
            for (int j = 0; j < 8; j++) nxt[j] = sU2[(i + 1) * 8 + j];
        }
        float va = P0[i >> 2] * Q0[i & 3];
        float vb = P1[i >> 2] * Q1[i & 3];
        unsigned long long vp0 = pack2(va, va);
        unsigned long long vp1 = pack2(vb, vb);
        #pragma unroll
        for (int j = 0; j < 8; j++) {
            asm("fma.rn.f32x2 %0, %1, %2, %0;" : "+l"(y0[2*j    ]) : "l"(buf[j].x), "l"(vp0));
            asm("fma.rn.f32x2 %0, %1, %2, %0;" : "+l"(y0[2*j + 1]) : "l"(buf[j].y), "l"(vp0));
            asm("fma.rn.f32x2 %0, %1, %2, %0;" : "+l"(y1[2*j    ]) : "l"(buf[j].x), "l"(vp1));
            asm("fma.rn.f32x2 %0, %1, %2, %0;" : "+l"(y1[2*j + 1]) : "l"(buf[j].y), "l"(vp1));
        }
        if (i < N_AMPS - 1) {
            #pragma unroll
            for (int j = 0; j < 8; j++) buf[j] = nxt[j];
        }
    }

    float4* out4 = reinterpret_cast<float4*>(out);
    out4[b0] = readout(y0);
    out4[b1] = readout(y1);
}

extern "C" void kernel_launch(void* const* d_in, const int* in_sizes, int n_in,
                              void* d_out, int out_size) {
    const float* inputs  = (const float*)d_in[0];   // (B, 4) float32
    const float* weights = (const float*)d_in[1];   // (6, 4, 3) float32
    float* out = (float*)d_out;                     // (B, 4) float32
    int B = in_sizes[0] / N_QUBITS;

    init_u_kernel<<<1, 256>>>(weights);
    int blocks = B / (THREADS * 2);                 // 262144 / 256 = 1024
    quantum_main_kernel<<<blocks, THREADS>>>(inputs, out);
}